// round 1
// baseline (speedup 1.0000x reference)
#include <cuda_runtime.h>

// Problem constants (fixed by the dataset)
#define B_  32
#define G_  256
#define P_  2048
#define NC_ 80

__device__ int    g_counts[B_ * NC_];
__device__ double g_sum;

// ---------------------------------------------------------------------------
// Kernel 1: per-batch class histogram of pre_label; also zero the accumulator.
// ---------------------------------------------------------------------------
__global__ void hist_kernel(const int* __restrict__ pre_label)
{
    const int b   = blockIdx.x;
    const int tid = threadIdx.x;
    __shared__ int hist[NC_];
    for (int i = tid; i < NC_; i += blockDim.x) hist[i] = 0;
    __syncthreads();
    const int* lab = pre_label + b * P_;
    for (int i = tid; i < P_; i += blockDim.x)
        atomicAdd(&hist[lab[i]], 1);
    __syncthreads();
    for (int i = tid; i < NC_; i += blockDim.x)
        g_counts[b * NC_ + i] = hist[i];
    if (b == 0 && tid == 0) g_sum = 0.0;
}

// ---------------------------------------------------------------------------
// Kernel 2: main GIoU + selection + weighted partial sum.
// grid = (P_/256, B_), block = 256. One thread per prediction p.
// ---------------------------------------------------------------------------
__global__ void __launch_bounds__(256)
giou_kernel(const float* __restrict__ imgs_box,
            const int*   __restrict__ img_labels,
            const float* __restrict__ pre_BOX,
            const int*   __restrict__ pre_label)
{
    const int b   = blockIdx.y;
    const int tid = threadIdx.x;
    const int p   = blockIdx.x * 256 + tid;

    __shared__ float4 tbox[G_];
    __shared__ int    tlab[G_];

    // Stage this batch's GT boxes + labels (G_=256 == blockDim).
    tbox[tid] = reinterpret_cast<const float4*>(imgs_box)[b * G_ + tid];
    tlab[tid] = img_labels[b * G_ + tid];
    __syncthreads();

    const float4 pb   = reinterpret_cast<const float4*>(pre_BOX)[b * P_ + p];
    const int    plab = pre_label[b * P_ + p];

    const float pw = fmaxf(pb.z - pb.x + 1.0f, 0.0f);
    const float ph = fmaxf(pb.w - pb.y + 1.0f, 0.0f);
    const float pa = pw * ph;

    float sel = 0.0f;
    bool  has = false;

    #pragma unroll 4
    for (int g = 0; g < G_; ++g) {
        if (tlab[g] != plab) continue;           // cheap reject: 1/80 hit rate
        const float4 tb = tbox[g];
        const float tw = fmaxf(tb.z - tb.x + 1.0f, 0.0f);
        const float th = fmaxf(tb.w - tb.y + 1.0f, 0.0f);
        const float ta = tw * th;

        const float iw = fmaxf(fminf(pb.z, tb.z) - fmaxf(pb.x, tb.x) + 1.0f, 0.0f);
        const float ih = fmaxf(fminf(pb.w, tb.w) - fmaxf(pb.y, tb.y) + 1.0f, 0.0f);
        const float inter = iw * ih;
        const float uni   = pa + ta - inter;

        const float iou = fmaxf(inter / pa, 1e-6f);   // reference divides by pred area

        const float ow = fmaxf(fmaxf(pb.z, tb.z) - fminf(pb.x, tb.x) + 1.0f, 0.0f);
        const float oh = fmaxf(fmaxf(pb.w, tb.w) - fminf(pb.y, tb.y) + 1.0f, 0.0f);
        const float outer = ow * oh;

        float giou = iou - (outer - uni) / outer;
        giou = fminf(fmaxf(giou, -1.0f), 1.0f);

        if (giou > 0.0f) { sel = giou; has = true; }  // ascending g => keeps LAST valid
    }

    const float loss = has ? (1.0f - sel) : 0.0f;
    const float w    = (float)g_counts[b * NC_ + plab];
    float partial    = w * loss;

    // Block reduction: warp shuffle, then cross-warp via shared.
    #pragma unroll
    for (int off = 16; off > 0; off >>= 1)
        partial += __shfl_down_sync(0xFFFFFFFFu, partial, off);

    __shared__ float wsum[8];
    const int wid = tid >> 5, lid = tid & 31;
    if (lid == 0) wsum[wid] = partial;
    __syncthreads();
    if (wid == 0) {
        float v = (lid < 8) ? wsum[lid] : 0.0f;
        #pragma unroll
        for (int off = 4; off > 0; off >>= 1)
            v += __shfl_down_sync(0xFFFFFFFFu, v, off);
        if (lid == 0) atomicAdd(&g_sum, (double)v);
    }
}

// ---------------------------------------------------------------------------
// Kernel 3: finalize scalar.
// ---------------------------------------------------------------------------
__global__ void finalize_kernel(float* __restrict__ out)
{
    *out = (float)(g_sum / (double)B_);
}

extern "C" void kernel_launch(void* const* d_in, const int* in_sizes, int n_in,
                              void* d_out, int out_size)
{
    const float* imgs_box   = (const float*)d_in[0];
    const int*   img_labels = (const int*)  d_in[1];
    const float* pre_BOX    = (const float*)d_in[2];
    const int*   pre_label  = (const int*)  d_in[3];
    float* out = (float*)d_out;

    hist_kernel<<<B_, 256>>>(pre_label);
    dim3 grid(P_ / 256, B_);
    giou_kernel<<<grid, 256>>>(imgs_box, img_labels, pre_BOX, pre_label);
    finalize_kernel<<<1, 1>>>(out);
}

// round 2
// speedup vs baseline: 3.1805x; 3.1805x over previous
#include <cuda_runtime.h>

#define B_  32
#define G_  256
#define P_  2048
#define NC_ 80

__device__ int      g_sorted[B_ * G_];        // GT indices grouped by class, ascending within class
__device__ int      g_off[B_ * (NC_ + 1)];    // per-batch class offsets into g_sorted
__device__ int      g_pcount[B_ * NC_];       // histogram of pre_label (the loss weights)
__device__ double   g_sum;
__device__ unsigned g_done;

// ---------------------------------------------------------------------------
// Kernel A: per-batch (1) stable counting sort of GT indices by class,
// (2) prediction-label histogram (weights), (3) reset accumulators.
// One block per batch, 256 threads.
// ---------------------------------------------------------------------------
__global__ void __launch_bounds__(G_)
group_kernel(const int* __restrict__ img_labels,
             const int* __restrict__ pre_label)
{
    const int b   = blockIdx.x;
    const int tid = threadIdx.x;     // == g index

    __shared__ int s_lab[G_];
    __shared__ int s_off[NC_ + 1];
    __shared__ int s_hist[NC_];
    __shared__ int s_phist[NC_];

    const int mylab = img_labels[b * G_ + tid];
    s_lab[tid] = mylab;
    if (tid < NC_) { s_hist[tid] = 0; s_phist[tid] = 0; }
    __syncthreads();

    // Stable rank among same-label GT entries
    int rank = 0;
    #pragma unroll 8
    for (int g = 0; g < G_; ++g)
        if (g < tid && s_lab[g] == mylab) ++rank;

    atomicAdd(&s_hist[mylab], 1);

    // Prediction-label histogram (weights): 2048 labels, 256 threads
    const int* plab = pre_label + b * P_;
    #pragma unroll
    for (int i = tid; i < P_; i += G_)
        atomicAdd(&s_phist[plab[i]], 1);
    __syncthreads();

    if (tid == 0) {
        int acc = 0;
        #pragma unroll
        for (int c = 0; c < NC_; ++c) { s_off[c] = acc; acc += s_hist[c]; }
        s_off[NC_] = acc;
    }
    __syncthreads();

    g_sorted[b * G_ + s_off[mylab] + rank] = tid;
    if (tid <= NC_) g_off[b * (NC_ + 1) + tid] = s_off[tid];
    if (tid < NC_)  g_pcount[b * NC_ + tid] = s_phist[tid];
    if (b == 0 && tid == 0) { g_sum = 0.0; g_done = 0u; }
}

// ---------------------------------------------------------------------------
// Kernel B: per-prediction GIoU against only same-class GT boxes, descending,
// early-exit on first giou>0 (== reference's "last valid index" selection).
// grid = (P_/256, B_), block = 256. Finalize fused via done-counter.
// ---------------------------------------------------------------------------
__global__ void __launch_bounds__(256)
giou_kernel(const float* __restrict__ imgs_box,
            const float* __restrict__ pre_BOX,
            const int*   __restrict__ pre_label,
            float*       __restrict__ out)
{
    const int b   = blockIdx.y;
    const int tid = threadIdx.x;
    const int p   = blockIdx.x * 256 + tid;

    __shared__ float4 tbox[G_];
    __shared__ int    s_sorted[G_];
    __shared__ int    s_off[NC_ + 1];

    tbox[tid]     = reinterpret_cast<const float4*>(imgs_box)[b * G_ + tid];
    s_sorted[tid] = g_sorted[b * G_ + tid];
    if (tid <= NC_) s_off[tid] = g_off[b * (NC_ + 1) + tid];
    __syncthreads();

    const float4 pb   = reinterpret_cast<const float4*>(pre_BOX)[b * P_ + p];
    const int    plab = pre_label[b * P_ + p];

    const float pw = fmaxf(pb.z - pb.x + 1.0f, 0.0f);
    const float ph = fmaxf(pb.w - pb.y + 1.0f, 0.0f);
    const float pa = pw * ph;

    const int start = s_off[plab];
    const int end   = s_off[plab + 1];

    float loss = 0.0f;
    for (int i = end - 1; i >= start; --i) {
        const float4 tb = tbox[s_sorted[i]];
        const float tw = fmaxf(tb.z - tb.x + 1.0f, 0.0f);
        const float th = fmaxf(tb.w - tb.y + 1.0f, 0.0f);
        const float ta = tw * th;

        const float iw = fmaxf(fminf(pb.z, tb.z) - fmaxf(pb.x, tb.x) + 1.0f, 0.0f);
        const float ih = fmaxf(fminf(pb.w, tb.w) - fmaxf(pb.y, tb.y) + 1.0f, 0.0f);
        const float inter = iw * ih;
        const float uni   = pa + ta - inter;

        const float iou = fmaxf(inter / pa, 1e-6f);   // reference divides by pred area

        const float ow = fmaxf(fmaxf(pb.z, tb.z) - fminf(pb.x, tb.x) + 1.0f, 0.0f);
        const float oh = fmaxf(fmaxf(pb.w, tb.w) - fminf(pb.y, tb.y) + 1.0f, 0.0f);
        const float outer = ow * oh;

        float giou = iou - (outer - uni) / outer;
        giou = fminf(fmaxf(giou, -1.0f), 1.0f);

        if (giou > 0.0f) { loss = 1.0f - giou; break; }
    }

    float partial = loss * (float)g_pcount[b * NC_ + plab];

    #pragma unroll
    for (int off = 16; off > 0; off >>= 1)
        partial += __shfl_down_sync(0xFFFFFFFFu, partial, off);

    __shared__ float wsum[8];
    const int wid = tid >> 5, lid = tid & 31;
    if (lid == 0) wsum[wid] = partial;
    __syncthreads();
    if (wid == 0) {
        float v = (lid < 8) ? wsum[lid] : 0.0f;
        #pragma unroll
        for (int off = 4; off > 0; off >>= 1)
            v += __shfl_down_sync(0xFFFFFFFFu, v, off);
        if (lid == 0) {
            atomicAdd(&g_sum, (double)v);
            __threadfence();
            unsigned t = atomicAdd(&g_done, 1u);
            if (t == gridDim.x * gridDim.y - 1u)
                *out = (float)(g_sum / (double)B_);
        }
    }
}

extern "C" void kernel_launch(void* const* d_in, const int* in_sizes, int n_in,
                              void* d_out, int out_size)
{
    const float* imgs_box   = (const float*)d_in[0];
    const int*   img_labels = (const int*)  d_in[1];
    const float* pre_BOX    = (const float*)d_in[2];
    const int*   pre_label  = (const int*)  d_in[3];
    float* out = (float*)d_out;

    group_kernel<<<B_, G_>>>(img_labels, pre_label);
    dim3 grid(P_ / 256, B_);
    giou_kernel<<<grid, 256>>>(imgs_box, pre_BOX, pre_label, out);
}

// round 4
// speedup vs baseline: 4.7025x; 1.4785x over previous
#include <cuda_runtime.h>

#define B_  32
#define G_  256
#define P_  2048
#define NC_ 80

#define CHUNKS_      4                    // blocks per batch
#define PRED_BLK_    (P_ / CHUNKS_)       // 512 preds per block
#define PRED_THD_    (PRED_BLK_ / 256)    // 2 preds per thread
#define NBLOCKS_     (CHUNKS_ * B_)       // 128

__device__ double   g_sum;     // zero at load; reset by last block each run
__device__ unsigned g_done;

// ---------------------------------------------------------------------------
// Single fused kernel. grid = (CHUNKS_, B_), block = 256.
// Each block redundantly builds its batch's class-grouped GT table + weight
// histogram in shared, then scores 512 predictions.
// Selection rule == reference: among GT with matching label and giou>0,
// take the one with the LARGEST g index (running max, no sort needed).
// ---------------------------------------------------------------------------
__global__ void __launch_bounds__(256)
fused_giou_kernel(const float* __restrict__ imgs_box,
                  const int*   __restrict__ img_labels,
                  const float* __restrict__ pre_BOX,
                  const int*   __restrict__ pre_label,
                  float*       __restrict__ out)
{
    const int b     = blockIdx.y;
    const int chunk = blockIdx.x;
    const int tid   = threadIdx.x;          // == GT index g during staging

    __shared__ float4 s_box[G_];            // GT boxes grouped by class (unordered within class)
    __shared__ int    s_g[G_];              // original g index of each grouped entry
    __shared__ int    s_off[NC_ + 1];       // class offsets
    __shared__ int    s_hist[NC_];
    __shared__ int    s_cnt[NC_];
    __shared__ int    s_phist[NC_];         // pre_label histogram (loss weights)
    __shared__ float  s_wsum[8];

    if (tid < NC_) { s_hist[tid] = 0; s_phist[tid] = 0; }
    __syncthreads();

    // --- GT class histogram + own box in registers ---
    const int    mylab = img_labels[b * G_ + tid];
    const float4 mybox = reinterpret_cast<const float4*>(imgs_box)[b * G_ + tid];
    atomicAdd(&s_hist[mylab], 1);

    // --- prediction-label histogram (weights): 2048 labels, int4-vectorized ---
    const int4* pl4 = reinterpret_cast<const int4*>(pre_label + b * P_);
    #pragma unroll
    for (int i = 0; i < P_ / (4 * 256); ++i) {       // 2 iterations
        const int4 v = pl4[i * 256 + tid];
        atomicAdd(&s_phist[v.x], 1);
        atomicAdd(&s_phist[v.y], 1);
        atomicAdd(&s_phist[v.z], 1);
        atomicAdd(&s_phist[v.w], 1);
    }
    __syncthreads();

    // --- exclusive prefix over 80 classes (thread 0, trivial) ---
    if (tid == 0) {
        int acc = 0;
        #pragma unroll
        for (int c = 0; c < NC_; ++c) { s_off[c] = acc; acc += s_hist[c]; }
        s_off[NC_] = acc;
    }
    __syncthreads();
    if (tid < NC_) s_cnt[tid] = s_off[tid];
    __syncthreads();

    // --- scatter GT boxes into class-grouped order ---
    {
        const int pos = atomicAdd(&s_cnt[mylab], 1);
        s_box[pos] = mybox;
        s_g[pos]   = tid;
    }
    __syncthreads();

    // --- score this block's 512 predictions ---
    float acc = 0.0f;
    #pragma unroll
    for (int j = 0; j < PRED_THD_; ++j) {
        const int p = chunk * PRED_BLK_ + j * 256 + tid;

        const float4 pb   = reinterpret_cast<const float4*>(pre_BOX)[b * P_ + p];
        const int    plab = pre_label[b * P_ + p];

        const float pw  = fmaxf(pb.z - pb.x + 1.0f, 0.0f);
        const float ph  = fmaxf(pb.w - pb.y + 1.0f, 0.0f);
        const float pa  = pw * ph;
        const float rpa = __fdividef(1.0f, pa);

        const int start = s_off[plab];
        const int end   = s_off[plab + 1];

        int   best_g    = -1;
        float best_giou = 0.0f;

        for (int i = start; i < end; ++i) {
            const float4 tb = s_box[i];
            const int    g  = s_g[i];

            const float tw = fmaxf(tb.z - tb.x + 1.0f, 0.0f);
            const float th = fmaxf(tb.w - tb.y + 1.0f, 0.0f);
            const float ta = tw * th;

            const float iw = fmaxf(fminf(pb.z, tb.z) - fmaxf(pb.x, tb.x) + 1.0f, 0.0f);
            const float ih = fmaxf(fminf(pb.w, tb.w) - fmaxf(pb.y, tb.y) + 1.0f, 0.0f);
            const float inter = iw * ih;
            const float uni   = pa + ta - inter;

            const float iou = fmaxf(inter * rpa, 1e-6f);   // reference: divide by pred area

            const float ow = fmaxf(fmaxf(pb.z, tb.z) - fminf(pb.x, tb.x) + 1.0f, 0.0f);
            const float oh = fmaxf(fmaxf(pb.w, tb.w) - fminf(pb.y, tb.y) + 1.0f, 0.0f);
            const float outer = ow * oh;

            float giou = iou - __fdividef(outer - uni, outer);
            giou = fminf(fmaxf(giou, -1.0f), 1.0f);

            if (giou > 0.0f && g > best_g) { best_g = g; best_giou = giou; }
        }

        const float loss = (best_g >= 0) ? (1.0f - best_giou) : 0.0f;
        acc += loss * (float)s_phist[plab];
    }

    // --- block reduction ---
    #pragma unroll
    for (int off = 16; off > 0; off >>= 1)
        acc += __shfl_down_sync(0xFFFFFFFFu, acc, off);

    const int wid = tid >> 5, lid = tid & 31;
    if (lid == 0) s_wsum[wid] = acc;
    __syncthreads();
    if (wid == 0) {
        float v = (lid < 8) ? s_wsum[lid] : 0.0f;
        #pragma unroll
        for (int off = 4; off > 0; off >>= 1)
            v += __shfl_down_sync(0xFFFFFFFFu, v, off);
        if (lid == 0) {
            atomicAdd(&g_sum, (double)v);
            __threadfence();
            const unsigned t = atomicAdd(&g_done, 1u);
            if (t == NBLOCKS_ - 1u) {
                // every contributing block fenced its add before incrementing
                // g_done, so a plain volatile read sees the full sum.
                const double total = *((volatile double*)&g_sum);
                *out = (float)(total / (double)B_);
                // reset for the next graph replay
                g_sum = 0.0;
                __threadfence();
                g_done = 0u;
            }
        }
    }
}

extern "C" void kernel_launch(void* const* d_in, const int* in_sizes, int n_in,
                              void* d_out, int out_size)
{
    const float* imgs_box   = (const float*)d_in[0];
    const int*   img_labels = (const int*)  d_in[1];
    const float* pre_BOX    = (const float*)d_in[2];
    const int*   pre_label  = (const int*)  d_in[3];
    float* out = (float*)d_out;

    dim3 grid(CHUNKS_, B_);
    fused_giou_kernel<<<grid, 256>>>(imgs_box, img_labels, pre_BOX, pre_label, out);
}